// round 1
// baseline (speedup 1.0000x reference)
#include <cuda_runtime.h>
#include <cstddef>

#define IMG 512
#define TILE 64
#define HALO 3
#define IN_TILE 70      // TILE + 2*HALO
#define SPITCH 72       // padded pitch, multiple of 4, 288B rows

__global__ __launch_bounds__(256, 2)
void conv7x7_kernel(const float* __restrict__ x,
                    const float* __restrict__ w,
                    float* __restrict__ out)
{
    __shared__ float s[IN_TILE][SPITCH];

    const int b    = blockIdx.z;
    const int row0 = blockIdx.y * TILE - HALO;   // global row of smem row 0
    const int col0 = blockIdx.x * TILE - HALO;   // global col of smem col 0
    const int tid  = threadIdx.x;

    const float* __restrict__ xb = x + (size_t)b * IMG * IMG;

    // Cooperative halo-tile load (zero-pad out of range)
    for (int i = tid; i < IN_TILE * IN_TILE; i += 256) {
        int r = i / IN_TILE;
        int c = i - r * IN_TILE;
        int gr = row0 + r;
        int gc = col0 + c;
        float v = 0.0f;
        if ((unsigned)gr < (unsigned)IMG && (unsigned)gc < (unsigned)IMG)
            v = __ldg(&xb[gr * IMG + gc]);
        s[r][c] = v;
    }

    // Weights -> registers (uniform address, L1 broadcast)
    float wt[49];
#pragma unroll
    for (int i = 0; i < 49; i++) wt[i] = __ldg(&w[i]);

    __syncthreads();

    const int tx = tid & 15;     // 0..15  -> output cols 4*tx .. 4*tx+3
    const int ty = tid >> 4;     // 0..15  -> output rows 4*ty .. 4*ty+3

    float acc[4][4] = {};

    // Slide over the 10 smem rows feeding this thread's 4 output rows.
    // smem row (4*ty + iy); weight row ky = iy - oy (valid 0..6).
#pragma unroll
    for (int iy = 0; iy < 10; iy++) {
        float rbuf[12];
        const float* sp = &s[4 * ty + iy][4 * tx];
#pragma unroll
        for (int j = 0; j < 3; j++) {
            float4 v = *reinterpret_cast<const float4*>(sp + 4 * j);
            rbuf[4 * j + 0] = v.x;
            rbuf[4 * j + 1] = v.y;
            rbuf[4 * j + 2] = v.z;
            rbuf[4 * j + 3] = v.w;
        }
#pragma unroll
        for (int oy = 0; oy < 4; oy++) {
            const int ky = iy - oy;
            if (ky >= 0 && ky < 7) {
#pragma unroll
                for (int kx = 0; kx < 7; kx++) {
                    const float wv = wt[ky * 7 + kx];
#pragma unroll
                    for (int ox = 0; ox < 4; ox++)
                        acc[oy][ox] = fmaf(wv, rbuf[ox + kx], acc[oy][ox]);
                }
            }
        }
    }

    // Vectorized store: output cols (64*bx + 4*tx) are 4-aligned.
    float* ob = out + (size_t)b * IMG * IMG
              + (size_t)(blockIdx.y * TILE + 4 * ty) * IMG
              + blockIdx.x * TILE + 4 * tx;
#pragma unroll
    for (int oy = 0; oy < 4; oy++) {
        float4 v = make_float4(acc[oy][0], acc[oy][1], acc[oy][2], acc[oy][3]);
        *reinterpret_cast<float4*>(ob + (size_t)oy * IMG) = v;
    }
}

extern "C" void kernel_launch(void* const* d_in, const int* in_sizes, int n_in,
                              void* d_out, int out_size)
{
    const float* x = (const float*)d_in[0];   // (64, 512, 512) fp32
    const float* w = (const float*)d_in[1];   // (7, 7) fp32
    float* out = (float*)d_out;               // (64, 512, 512) fp32

    dim3 grid(IMG / TILE, IMG / TILE, 64);    // 8 x 8 x 64
    conv7x7_kernel<<<grid, 256>>>(x, w, out);
}

// round 3
// speedup vs baseline: 1.5239x; 1.5239x over previous
#include <cuda_runtime.h>
#include <cstddef>

#define IMG 512
#define TILE 64
#define HALO 3
#define IN_TILE 70      // TILE + 2*HALO
#define SPITCH 72       // padded pitch, 288B rows -> conflict-free float4 lanes

__constant__ float c_w[49];

__global__ __launch_bounds__(256, 3)
void conv7x7_kernel(const float* __restrict__ x,
                    float* __restrict__ out)
{
    __shared__ float s[IN_TILE][SPITCH];

    const int b    = blockIdx.z;
    const int row0 = blockIdx.y * TILE - HALO;
    const int col0 = blockIdx.x * TILE - HALO;
    const int tid  = threadIdx.x;

    const float* __restrict__ xb = x + (size_t)b * IMG * IMG;

    // Cooperative halo-tile load (zero-pad out of range)
    for (int i = tid; i < IN_TILE * IN_TILE; i += 256) {
        int r = i / IN_TILE;
        int c = i - r * IN_TILE;
        int gr = row0 + r;
        int gc = col0 + c;
        float v = 0.0f;
        if ((unsigned)gr < (unsigned)IMG && (unsigned)gc < (unsigned)IMG)
            v = __ldg(&xb[gr * IMG + gc]);
        s[r][c] = v;
    }

    __syncthreads();

    const int tx = tid & 15;     // output cols 4*tx .. 4*tx+3
    const int ty = tid >> 4;     // output rows 4*ty .. 4*ty+3

    float acc[4][4] = {};

    // Slide over the 10 smem rows feeding this thread's 4 output rows.
    // smem row (4*ty + iy); weight row ky = iy - oy (valid 0..6).
#pragma unroll
    for (int iy = 0; iy < 10; iy++) {
        float rbuf[12];
        const float* sp = &s[4 * ty + iy][4 * tx];
#pragma unroll
        for (int j = 0; j < 3; j++) {
            float4 v = *reinterpret_cast<const float4*>(sp + 4 * j);
            rbuf[4 * j + 0] = v.x;
            rbuf[4 * j + 1] = v.y;
            rbuf[4 * j + 2] = v.z;
            rbuf[4 * j + 3] = v.w;
        }
#pragma unroll
        for (int oy = 0; oy < 4; oy++) {
            const int ky = iy - oy;
            if (ky >= 0 && ky < 7) {
#pragma unroll
                for (int kx = 0; kx < 7; kx++) {
                    const float wv = c_w[ky * 7 + kx];   // uniform: LDCU -> UR
#pragma unroll
                    for (int ox = 0; ox < 4; ox++)
                        acc[oy][ox] = fmaf(wv, rbuf[ox + kx], acc[oy][ox]);
                }
            }
        }
    }

    float* ob = out + (size_t)b * IMG * IMG
              + (size_t)(blockIdx.y * TILE + 4 * ty) * IMG
              + blockIdx.x * TILE + 4 * tx;
#pragma unroll
    for (int oy = 0; oy < 4; oy++) {
        float4 v = make_float4(acc[oy][0], acc[oy][1], acc[oy][2], acc[oy][3]);
        *reinterpret_cast<float4*>(ob + (size_t)oy * IMG) = v;
    }
}

extern "C" void kernel_launch(void* const* d_in, const int* in_sizes, int n_in,
                              void* d_out, int out_size)
{
    const float* x = (const float*)d_in[0];   // (64, 512, 512) fp32
    const float* w = (const float*)d_in[1];   // (7, 7) fp32
    float* out = (float*)d_out;               // (64, 512, 512) fp32

    // Stage weights into constant memory (async D2D copy, graph-capturable).
    cudaMemcpyToSymbolAsync(c_w, w, 49 * sizeof(float), 0,
                            cudaMemcpyDeviceToDevice, 0);

    dim3 grid(IMG / TILE, IMG / TILE, 64);    // 8 x 8 x 64
    conv7x7_kernel<<<grid, 256>>>(x, out);
}